// round 1
// baseline (speedup 1.0000x reference)
#include <cuda_runtime.h>
#include <math_constants.h>

// Problem constants
#define BSZ 2
#define SEQ 2048
#define HID 1024
#define NH 16
#define HD 64
#define MTOT (BSZ * SEQ)   // 4096

// Scratch (allocation-free rule: __device__ globals)
__device__ float g_Q[BSZ * NH * SEQ * HD];
__device__ float g_K[BSZ * NH * SEQ * HD];
__device__ float g_V[BSZ * NH * SEQ * HD];
__device__ float g_ctx[BSZ * SEQ * HID];

// ---------------------------------------------------------------------------
// SGEMM: C[M=4096, N=1024] = A[M,1024] @ W[1024,1024] + bias
// BM=128, BN=128, BK=16, 256 threads, 8x8 microtile per thread.
// LAYOUT 0: C[m*1024+n]   (plain row-major [B,S,HID])
// LAYOUT 1: scatter to [B,H,S,D]
// ---------------------------------------------------------------------------
template <int LAYOUT>
__global__ void __launch_bounds__(256) sgemm_bias_kernel(
    const float* __restrict__ A, const float* __restrict__ W,
    const float* __restrict__ bias, float* __restrict__ C)
{
    __shared__ __align__(16) float As[16][129];  // transposed A tile [k][m]
    __shared__ __align__(16) float Bs[16][128];  // [k][n]

    const int tid = threadIdx.x;
    const int tx = tid & 15;
    const int ty = tid >> 4;
    const int m0 = blockIdx.y * 128;
    const int n0 = blockIdx.x * 128;

    float acc[8][8];
#pragma unroll
    for (int i = 0; i < 8; i++)
#pragma unroll
        for (int j = 0; j < 8; j++) acc[i][j] = 0.f;

    for (int k0 = 0; k0 < 1024; k0 += 16) {
        // Load A tile: 128x16 = 512 float4, 2 per thread, store transposed
#pragma unroll
        for (int it = 0; it < 2; it++) {
            int l = tid + it * 256;
            int row = l >> 2;
            int cg = (l & 3) * 4;
            float4 v = *(const float4*)&A[(size_t)(m0 + row) * 1024 + k0 + cg];
            As[cg + 0][row] = v.x;
            As[cg + 1][row] = v.y;
            As[cg + 2][row] = v.z;
            As[cg + 3][row] = v.w;
        }
        // Load W tile: 16x128 = 512 float4, 2 per thread
#pragma unroll
        for (int it = 0; it < 2; it++) {
            int l = tid + it * 256;
            int row = l >> 5;
            int cg = (l & 31) * 4;
            *(float4*)&Bs[row][cg] =
                *(const float4*)&W[(size_t)(k0 + row) * 1024 + n0 + cg];
        }
        __syncthreads();

#pragma unroll
        for (int kk = 0; kk < 16; kk++) {
            float a[8], b[8];
#pragma unroll
            for (int i = 0; i < 8; i++) a[i] = As[kk][ty * 8 + i];
            *(float4*)&b[0] = *(float4*)&Bs[kk][tx * 8];
            *(float4*)&b[4] = *(float4*)&Bs[kk][tx * 8 + 4];
#pragma unroll
            for (int i = 0; i < 8; i++)
#pragma unroll
                for (int j = 0; j < 8; j++) acc[i][j] = fmaf(a[i], b[j], acc[i][j]);
        }
        __syncthreads();
    }

    // Epilogue
#pragma unroll
    for (int i = 0; i < 8; i++) {
        int m = m0 + ty * 8 + i;
#pragma unroll
        for (int j = 0; j < 8; j++) {
            int n = n0 + tx * 8 + j;
            float val = acc[i][j] + bias[n];
            if (LAYOUT == 0) {
                C[(size_t)m * 1024 + n] = val;
            } else {
                int b = m >> 11;        // / SEQ
                int s = m & (SEQ - 1);
                int h = n >> 6;         // / HD
                int d = n & (HD - 1);
                C[((((size_t)b * NH + h) * SEQ + s) * HD) + d] = val;
            }
        }
    }
}

// ---------------------------------------------------------------------------
// Axial RoPE on Q and K, in place, layout [B,H,S,D].
// First 60 dims: 3 segments of 20 (frame/height/width positions).
// Within a segment: out[2i]   = x[2i]*cos(p*om[(2i)%10])   - x[2i+1]*sin(p*om[(2i)%10])
//                   out[2i+1] = x[2i+1]*cos(p*om[(2i+1)%10]) + x[2i]*sin(p*om[(2i+1)%10])
// om[j] = 10000^(-j/10). Dims 60..63 untouched.
// ---------------------------------------------------------------------------
__global__ void rope_kernel(float* __restrict__ Q, float* __restrict__ K)
{
    const int PAIRS = 30;
    const int TOK = BSZ * NH * SEQ;            // 65536
    const int TOTAL = 2 * TOK * PAIRS;
    int idx = blockIdx.x * blockDim.x + threadIdx.x;
    if (idx >= TOTAL) return;

    float* base = (idx < TOK * PAIRS) ? Q : K;
    int r = (idx < TOK * PAIRS) ? idx : (idx - TOK * PAIRS);
    int token = r / PAIRS;
    int pair = r - token * PAIRS;
    int d0 = pair * 2;                 // 0..58
    int seg = d0 / 20;
    int dl = d0 - seg * 20;            // even, 0..18

    int s = token & (SEQ - 1);
    int frame = s >> 8;                // / 256
    int rem = s & 255;
    int hpos = rem >> 4;
    int wpos = rem & 15;
    float pos = (float)(seg == 0 ? frame : (seg == 1 ? hpos : wpos));

    int je = dl % 10;                  // even element's omega index
    const float lg = -0.9210340371976184f;  // -ln(10000)/10
    float om_e = expf(lg * (float)je);
    float om_o = expf(lg * (float)(je + 1));
    float th_e = pos * om_e;
    float th_o = pos * om_o;
    float se, ce, so, co;
    sincosf(th_e, &se, &ce);
    sincosf(th_o, &so, &co);

    float2 x = *(float2*)&base[(size_t)token * HD + d0];
    float2 y;
    y.x = x.x * ce - x.y * se;
    y.y = x.y * co + x.x * so;
    *(float2*)&base[(size_t)token * HD + d0] = y;
}

// ---------------------------------------------------------------------------
// Fused flash attention, fp32. One block = 64 queries of one (b,h).
// 256 threads, 4x4 microtile per thread, online softmax.
// Output written directly to ctx in [B,S,HID] layout.
// Dynamic smem layout (floats):
//   Qs[64][64]  (transposed: [d][row])
//   Ks[64][65]  (transposed: [d][key])
//   Vs[64][64]  ([key][d])
//   Ss[64][65]  (probs [row][key])
// ---------------------------------------------------------------------------
__global__ void __launch_bounds__(256) attn_kernel(
    const float* __restrict__ Q, const float* __restrict__ K,
    const float* __restrict__ V, float* __restrict__ ctx)
{
    extern __shared__ float sm[];
    float (*Qs)[64] = (float(*)[64])(sm);
    float (*Ks)[65] = (float(*)[65])(sm + 4096);
    float (*Vs)[64] = (float(*)[64])(sm + 4096 + 4160);
    float (*Ss)[65] = (float(*)[65])(sm + 4096 + 4160 + 4096);

    const int tid = threadIdx.x;
    const int tx = tid & 15;
    const int ty = tid >> 4;
    const int qt = blockIdx.x;
    const int h = blockIdx.y;
    const int b = blockIdx.z;

    const float* Qb = Q + (((size_t)b * NH + h) * SEQ + qt * 64) * HD;
    const float* Kb = K + ((size_t)b * NH + h) * SEQ * HD;
    const float* Vb = V + ((size_t)b * NH + h) * SEQ * HD;

    // Load Q tile transposed: 64x64 = 1024 float4, 4 per thread
#pragma unroll
    for (int it = 0; it < 4; it++) {
        int l = tid + it * 256;
        int row = l >> 4;
        int cg = (l & 15) * 4;
        float4 v = *(const float4*)&Qb[(size_t)row * HD + cg];
        Qs[cg + 0][row] = v.x;
        Qs[cg + 1][row] = v.y;
        Qs[cg + 2][row] = v.z;
        Qs[cg + 3][row] = v.w;
    }

    float m_i[4], l_i[4], o[4][4];
#pragma unroll
    for (int i = 0; i < 4; i++) {
        m_i[i] = -CUDART_INF_F;
        l_i[i] = 0.f;
#pragma unroll
        for (int j = 0; j < 4; j++) o[i][j] = 0.f;
    }
    __syncthreads();

    for (int j0 = 0; j0 < SEQ; j0 += 64) {
        // Load K (transposed) and V (natural) tiles
#pragma unroll
        for (int it = 0; it < 4; it++) {
            int l = tid + it * 256;
            int row = l >> 4;
            int cg = (l & 15) * 4;
            float4 kv = *(const float4*)&Kb[(size_t)(j0 + row) * HD + cg];
            Ks[cg + 0][row] = kv.x;
            Ks[cg + 1][row] = kv.y;
            Ks[cg + 2][row] = kv.z;
            Ks[cg + 3][row] = kv.w;
            *(float4*)&Vs[row][cg] =
                *(const float4*)&Vb[(size_t)(j0 + row) * HD + cg];
        }
        __syncthreads();

        // QK^T : sc[i][j] for rows ty*4+i, keys tx*4+j
        float sc[4][4];
#pragma unroll
        for (int i = 0; i < 4; i++)
#pragma unroll
            for (int j = 0; j < 4; j++) sc[i][j] = 0.f;

#pragma unroll 8
        for (int d = 0; d < 64; d++) {
            float a[4], bb[4];
#pragma unroll
            for (int i = 0; i < 4; i++) a[i] = Qs[d][ty * 4 + i];
#pragma unroll
            for (int j = 0; j < 4; j++) bb[j] = Ks[d][tx * 4 + j];
#pragma unroll
            for (int i = 0; i < 4; i++)
#pragma unroll
                for (int j = 0; j < 4; j++) sc[i][j] = fmaf(a[i], bb[j], sc[i][j]);
        }

        // Online softmax per row (reduction over the 16 lanes sharing ty)
#pragma unroll
        for (int i = 0; i < 4; i++) {
            float pm = -CUDART_INF_F;
#pragma unroll
            for (int j = 0; j < 4; j++) {
                sc[i][j] *= 0.125f;  // 1/sqrt(64)
                pm = fmaxf(pm, sc[i][j]);
            }
#pragma unroll
            for (int d = 1; d < 16; d <<= 1)
                pm = fmaxf(pm, __shfl_xor_sync(0xffffffffu, pm, d));

            float mn = fmaxf(m_i[i], pm);
            float corr = __expf(m_i[i] - mn);
            m_i[i] = mn;

            float ps = 0.f;
#pragma unroll
            for (int j = 0; j < 4; j++) {
                sc[i][j] = __expf(sc[i][j] - mn);
                ps += sc[i][j];
            }
#pragma unroll
            for (int d = 1; d < 16; d <<= 1)
                ps += __shfl_xor_sync(0xffffffffu, ps, d);

            l_i[i] = l_i[i] * corr + ps;
#pragma unroll
            for (int j = 0; j < 4; j++) {
                o[i][j] *= corr;
                Ss[ty * 4 + i][tx * 4 + j] = sc[i][j];
            }
        }
        __syncthreads();

        // PV: o[i][j] += P[row][k] * V[k][col]
#pragma unroll 8
        for (int kk = 0; kk < 64; kk++) {
            float a[4], bb[4];
#pragma unroll
            for (int i = 0; i < 4; i++) a[i] = Ss[ty * 4 + i][kk];
            *(float4*)&bb[0] = *(float4*)&Vs[kk][tx * 4];
#pragma unroll
            for (int i = 0; i < 4; i++)
#pragma unroll
                for (int j = 0; j < 4; j++) o[i][j] = fmaf(a[i], bb[j], o[i][j]);
        }
        __syncthreads();
    }

    // Write ctx in [B,S,HID] layout
#pragma unroll
    for (int i = 0; i < 4; i++) {
        float inv = 1.f / l_i[i];
        int srow = qt * 64 + ty * 4 + i;
#pragma unroll
        for (int j = 0; j < 4; j++) {
            ctx[((size_t)b * SEQ + srow) * HID + h * HD + tx * 4 + j] = o[i][j] * inv;
        }
    }
}

// ---------------------------------------------------------------------------
extern "C" void kernel_launch(void* const* d_in, const int* in_sizes, int n_in,
                              void* d_out, int out_size)
{
    const float* hidden = (const float*)d_in[0];
    const float* Wq = (const float*)d_in[1];
    const float* bq = (const float*)d_in[2];
    const float* Wk = (const float*)d_in[3];
    const float* bk = (const float*)d_in[4];
    const float* Wv = (const float*)d_in[5];
    const float* bv = (const float*)d_in[6];
    const float* Wo = (const float*)d_in[7];
    const float* bo = (const float*)d_in[8];
    float* out = (float*)d_out;

    float *pQ, *pK, *pV, *pCtx;
    cudaGetSymbolAddress((void**)&pQ, g_Q);
    cudaGetSymbolAddress((void**)&pK, g_K);
    cudaGetSymbolAddress((void**)&pV, g_V);
    cudaGetSymbolAddress((void**)&pCtx, g_ctx);

    dim3 ggrid(HID / 128, MTOT / 128);  // (8, 32)

    // QKV projections (+ bias), scattered to [B,H,S,D]
    sgemm_bias_kernel<1><<<ggrid, 256>>>(hidden, Wq, bq, pQ);
    sgemm_bias_kernel<1><<<ggrid, 256>>>(hidden, Wk, bk, pK);
    sgemm_bias_kernel<1><<<ggrid, 256>>>(hidden, Wv, bv, pV);

    // RoPE on Q and K
    {
        const int total = 2 * (BSZ * NH * SEQ) * 30;
        rope_kernel<<<(total + 255) / 256, 256>>>(pQ, pK);
    }

    // Fused attention -> ctx [B,S,HID]
    {
        const int smem_bytes = (4096 + 4160 + 4096 + 4160) * sizeof(float);  // 66048
        static int attr_set = 0;
        cudaFuncSetAttribute(attn_kernel,
                             cudaFuncAttributeMaxDynamicSharedMemorySize,
                             smem_bytes);
        (void)attr_set;
        dim3 agrid(SEQ / 64, NH, BSZ);  // (32, 16, 2)
        attn_kernel<<<agrid, 256, smem_bytes>>>(pQ, pK, pV, pCtx);
    }

    // Output projection
    sgemm_bias_kernel<0><<<ggrid, 256>>>(pCtx, Wo, bo, out);
}

// round 2
// speedup vs baseline: 5.0826x; 5.0826x over previous
#include <cuda_runtime.h>
#include <math_constants.h>

#define BSZ 2
#define SEQ 2048
#define HID 1024
#define NH 16
#define HD 64
#define MTOT (BSZ * SEQ)   // 4096

// Scratch
__device__ float g_Q[BSZ * NH * SEQ * HD];
__device__ float g_K[BSZ * NH * SEQ * HD];
__device__ float g_V[BSZ * NH * SEQ * HD];
__device__ float g_ctx[BSZ * SEQ * HID];

__device__ __forceinline__ unsigned f2tf32(float x) {
    unsigned r;
    asm("cvt.rna.tf32.f32 %0, %1;" : "=r"(r) : "f"(x));
    return r;
}

__device__ __forceinline__ void mma_tf32(float c[4], const unsigned a[4],
                                         unsigned b0, unsigned b1) {
    asm volatile(
        "mma.sync.aligned.m16n8k8.row.col.f32.tf32.tf32.f32 "
        "{%0,%1,%2,%3}, {%4,%5,%6,%7}, {%8,%9}, {%0,%1,%2,%3};\n"
        : "+f"(c[0]), "+f"(c[1]), "+f"(c[2]), "+f"(c[3])
        : "r"(a[0]), "r"(a[1]), "r"(a[2]), "r"(a[3]), "r"(b0), "r"(b1));
}

// ---------------------------------------------------------------------------
// tf32 GEMM: C[4096,1024] = A @ W + bias. 128x128 tile, BK=32, 256 threads.
// LAYOUT 0: row-major [B,S,HID]; LAYOUT 1: scatter to [B,H,S,D].
// ---------------------------------------------------------------------------
template <int LAYOUT>
__global__ void __launch_bounds__(256) gemm_tf32_kernel(
    const float* __restrict__ A, const float* __restrict__ W,
    const float* __restrict__ bias, float* __restrict__ C)
{
    __shared__ unsigned As[128][36];   // [m][k], pad 4 -> frag bank 4g+t
    __shared__ unsigned Bs[32][136];   // [k][n], pad 8 -> frag bank 8t+g

    const int tid = threadIdx.x;
    const int warp = tid >> 5, lane = tid & 31;
    const int g = lane >> 2, t = lane & 3;
    const int wm = (warp >> 2) * 64;   // warp m offset (2 rows of warps)
    const int wn = (warp & 3) * 32;    // warp n offset (4 cols)
    const int m0 = blockIdx.y * 128;
    const int n0 = blockIdx.x * 128;

    float acc[4][4][4];
#pragma unroll
    for (int mt = 0; mt < 4; mt++)
#pragma unroll
        for (int nt = 0; nt < 4; nt++)
#pragma unroll
            for (int i = 0; i < 4; i++) acc[mt][nt][i] = 0.f;

    for (int k0 = 0; k0 < 1024; k0 += 32) {
        // A tile 128x32: 1024 float4, 4/thread
#pragma unroll
        for (int it = 0; it < 4; it++) {
            int l = tid + it * 256;
            int row = l >> 3;
            int cg = (l & 7) * 4;
            float4 v = *(const float4*)&A[(size_t)(m0 + row) * 1024 + k0 + cg];
            As[row][cg + 0] = f2tf32(v.x);
            As[row][cg + 1] = f2tf32(v.y);
            As[row][cg + 2] = f2tf32(v.z);
            As[row][cg + 3] = f2tf32(v.w);
        }
        // W tile 32x128
#pragma unroll
        for (int it = 0; it < 4; it++) {
            int l = tid + it * 256;
            int row = l >> 5;
            int cg = (l & 31) * 4;
            float4 v = *(const float4*)&W[(size_t)(k0 + row) * 1024 + n0 + cg];
            Bs[row][cg + 0] = f2tf32(v.x);
            Bs[row][cg + 1] = f2tf32(v.y);
            Bs[row][cg + 2] = f2tf32(v.z);
            Bs[row][cg + 3] = f2tf32(v.w);
        }
        __syncthreads();

#pragma unroll
        for (int ks = 0; ks < 4; ks++) {
            const int kk = ks * 8;
            unsigned af[4][4];
#pragma unroll
            for (int mt = 0; mt < 4; mt++) {
                int r = wm + mt * 16 + g;
                af[mt][0] = As[r][kk + t];
                af[mt][1] = As[r + 8][kk + t];
                af[mt][2] = As[r][kk + t + 4];
                af[mt][3] = As[r + 8][kk + t + 4];
            }
#pragma unroll
            for (int nt = 0; nt < 4; nt++) {
                unsigned b0 = Bs[kk + t][wn + nt * 8 + g];
                unsigned b1 = Bs[kk + t + 4][wn + nt * 8 + g];
#pragma unroll
                for (int mt = 0; mt < 4; mt++)
                    mma_tf32(acc[mt][nt], af[mt], b0, b1);
            }
        }
        __syncthreads();
    }

    // Epilogue
#pragma unroll
    for (int mt = 0; mt < 4; mt++) {
#pragma unroll
        for (int hi = 0; hi < 2; hi++) {
            int m = m0 + wm + mt * 16 + g + hi * 8;
#pragma unroll
            for (int nt = 0; nt < 4; nt++) {
                int n = n0 + wn + nt * 8 + 2 * t;
                float2 val;
                val.x = acc[mt][nt][hi * 2 + 0] + bias[n];
                val.y = acc[mt][nt][hi * 2 + 1] + bias[n + 1];
                if (LAYOUT == 0) {
                    *(float2*)&C[(size_t)m * 1024 + n] = val;
                } else {
                    int b = m >> 11;
                    int s = m & (SEQ - 1);
                    int h = n >> 6;
                    int d = n & (HD - 1);
                    *(float2*)&C[((((size_t)b * NH + h) * SEQ + s) * HD) + d] = val;
                }
            }
        }
    }
}

// ---------------------------------------------------------------------------
// Axial RoPE (unchanged)
// ---------------------------------------------------------------------------
__global__ void rope_kernel(float* __restrict__ Q, float* __restrict__ K)
{
    const int PAIRS = 30;
    const int TOK = BSZ * NH * SEQ;
    const int TOTAL = 2 * TOK * PAIRS;
    int idx = blockIdx.x * blockDim.x + threadIdx.x;
    if (idx >= TOTAL) return;

    float* base = (idx < TOK * PAIRS) ? Q : K;
    int r = (idx < TOK * PAIRS) ? idx : (idx - TOK * PAIRS);
    int token = r / PAIRS;
    int pair = r - token * PAIRS;
    int d0 = pair * 2;
    int seg = d0 / 20;
    int dl = d0 - seg * 20;

    int s = token & (SEQ - 1);
    int frame = s >> 8;
    int rem = s & 255;
    int hpos = rem >> 4;
    int wpos = rem & 15;
    float pos = (float)(seg == 0 ? frame : (seg == 1 ? hpos : wpos));

    int je = dl % 10;
    const float lg = -0.9210340371976184f;  // -ln(10000)/10
    float om_e = expf(lg * (float)je);
    float om_o = expf(lg * (float)(je + 1));
    float se, ce, so, co;
    sincosf(pos * om_e, &se, &ce);
    sincosf(pos * om_o, &so, &co);

    float2 x = *(float2*)&base[(size_t)token * HD + d0];
    float2 y;
    y.x = x.x * ce - x.y * se;
    y.y = x.y * co + x.x * so;
    *(float2*)&base[(size_t)token * HD + d0] = y;
}

// ---------------------------------------------------------------------------
// Flash attention with tf32 mma. Block: 128 queries, 4 warps (32 rows each).
// Key tiles of 64. Online softmax in registers. P staged via smem (tf32).
// Dynamic smem (unsigned words):
//   Qs[128][68], Ks[64][68] ([key][d]), Vs[64][68] ([d][key]), Ss[128][68]
// ---------------------------------------------------------------------------
__global__ void __launch_bounds__(128) attn_tf32_kernel(
    const float* __restrict__ Q, const float* __restrict__ K,
    const float* __restrict__ V, float* __restrict__ ctx)
{
    extern __shared__ unsigned smu[];
    unsigned (*Qs)[68] = (unsigned(*)[68])(smu);
    unsigned (*Ks)[68] = (unsigned(*)[68])(smu + 128 * 68);
    unsigned (*Vs)[68] = (unsigned(*)[68])(smu + 128 * 68 + 64 * 68);
    unsigned (*Ss)[68] = (unsigned(*)[68])(smu + 128 * 68 + 2 * 64 * 68);

    const int tid = threadIdx.x;
    const int warp = tid >> 5, lane = tid & 31;
    const int g = lane >> 2, t = lane & 3;
    const int w32 = warp * 32;
    const int qt = blockIdx.x;
    const int h = blockIdx.y;
    const int b = blockIdx.z;

    const float* Qb = Q + (((size_t)b * NH + h) * SEQ + qt * 128) * HD;
    const float* Kb = K + ((size_t)b * NH + h) * SEQ * HD;
    const float* Vb = V + ((size_t)b * NH + h) * SEQ * HD;

    // Load Q tile 128x64 -> tf32
#pragma unroll
    for (int it = 0; it < 16; it++) {
        int l = tid + it * 128;
        int row = l >> 4;
        int cg = (l & 15) * 4;
        float4 v = *(const float4*)&Qb[(size_t)row * HD + cg];
        Qs[row][cg + 0] = f2tf32(v.x);
        Qs[row][cg + 1] = f2tf32(v.y);
        Qs[row][cg + 2] = f2tf32(v.z);
        Qs[row][cg + 3] = f2tf32(v.w);
    }

    float m_i[4], l_i[4], o[2][8][4];
#pragma unroll
    for (int i = 0; i < 4; i++) { m_i[i] = -CUDART_INF_F; l_i[i] = 0.f; }
#pragma unroll
    for (int mt = 0; mt < 2; mt++)
#pragma unroll
        for (int nt = 0; nt < 8; nt++)
#pragma unroll
            for (int i = 0; i < 4; i++) o[mt][nt][i] = 0.f;
    __syncthreads();

    for (int j0 = 0; j0 < SEQ; j0 += 64) {
        // K tile natural [key][d]; V tile transposed [d][key]
#pragma unroll
        for (int it = 0; it < 8; it++) {
            int l = tid + it * 128;
            int row = l >> 4;
            int cg = (l & 15) * 4;
            float4 kv = *(const float4*)&Kb[(size_t)(j0 + row) * HD + cg];
            Ks[row][cg + 0] = f2tf32(kv.x);
            Ks[row][cg + 1] = f2tf32(kv.y);
            Ks[row][cg + 2] = f2tf32(kv.z);
            Ks[row][cg + 3] = f2tf32(kv.w);
            float4 vv = *(const float4*)&Vb[(size_t)(j0 + row) * HD + cg];
            Vs[cg + 0][row] = f2tf32(vv.x);
            Vs[cg + 1][row] = f2tf32(vv.y);
            Vs[cg + 2][row] = f2tf32(vv.z);
            Vs[cg + 3][row] = f2tf32(vv.w);
        }
        __syncthreads();

        // S = Q K^T
        float sc[2][8][4];
#pragma unroll
        for (int mt = 0; mt < 2; mt++)
#pragma unroll
            for (int nt = 0; nt < 8; nt++)
#pragma unroll
                for (int i = 0; i < 4; i++) sc[mt][nt][i] = 0.f;

#pragma unroll
        for (int ks = 0; ks < 8; ks++) {
            const int kk = ks * 8;
            unsigned af[2][4];
#pragma unroll
            for (int mt = 0; mt < 2; mt++) {
                int r = w32 + mt * 16 + g;
                af[mt][0] = Qs[r][kk + t];
                af[mt][1] = Qs[r + 8][kk + t];
                af[mt][2] = Qs[r][kk + t + 4];
                af[mt][3] = Qs[r + 8][kk + t + 4];
            }
#pragma unroll
            for (int nt = 0; nt < 8; nt++) {
                unsigned b0 = Ks[nt * 8 + g][kk + t];
                unsigned b1 = Ks[nt * 8 + g][kk + t + 4];
#pragma unroll
                for (int mt = 0; mt < 2; mt++)
                    mma_tf32(sc[mt][nt], af[mt], b0, b1);
            }
        }

        // Online softmax; write P (tf32) to Ss
#pragma unroll
        for (int mt = 0; mt < 2; mt++) {
#pragma unroll
            for (int hi = 0; hi < 2; hi++) {
                const int ri = mt * 2 + hi;
                float pm = -CUDART_INF_F;
#pragma unroll
                for (int nt = 0; nt < 8; nt++) {
                    sc[mt][nt][hi * 2 + 0] *= 0.125f;
                    sc[mt][nt][hi * 2 + 1] *= 0.125f;
                    pm = fmaxf(pm, fmaxf(sc[mt][nt][hi * 2], sc[mt][nt][hi * 2 + 1]));
                }
                pm = fmaxf(pm, __shfl_xor_sync(0xffffffffu, pm, 1));
                pm = fmaxf(pm, __shfl_xor_sync(0xffffffffu, pm, 2));

                float mn = fmaxf(m_i[ri], pm);
                float corr = __expf(m_i[ri] - mn);
                m_i[ri] = mn;

                float ps = 0.f;
                int row = w32 + mt * 16 + g + hi * 8;
#pragma unroll
                for (int nt = 0; nt < 8; nt++) {
                    float p0 = __expf(sc[mt][nt][hi * 2 + 0] - mn);
                    float p1 = __expf(sc[mt][nt][hi * 2 + 1] - mn);
                    ps += p0 + p1;
                    Ss[row][nt * 8 + 2 * t + 0] = f2tf32(p0);
                    Ss[row][nt * 8 + 2 * t + 1] = f2tf32(p1);
                }
                ps += __shfl_xor_sync(0xffffffffu, ps, 1);
                ps += __shfl_xor_sync(0xffffffffu, ps, 2);
                l_i[ri] = l_i[ri] * corr + ps;

#pragma unroll
                for (int nt = 0; nt < 8; nt++) {
                    o[mt][nt][hi * 2 + 0] *= corr;
                    o[mt][nt][hi * 2 + 1] *= corr;
                }
            }
        }
        __syncwarp();

        // O += P V   (A = Ss rows, B = Vs[d][key])
#pragma unroll
        for (int ks = 0; ks < 8; ks++) {
            const int kk = ks * 8;
            unsigned af[2][4];
#pragma unroll
            for (int mt = 0; mt < 2; mt++) {
                int r = w32 + mt * 16 + g;
                af[mt][0] = Ss[r][kk + t];
                af[mt][1] = Ss[r + 8][kk + t];
                af[mt][2] = Ss[r][kk + t + 4];
                af[mt][3] = Ss[r + 8][kk + t + 4];
            }
#pragma unroll
            for (int nt = 0; nt < 8; nt++) {
                unsigned b0 = Vs[nt * 8 + g][kk + t];
                unsigned b1 = Vs[nt * 8 + g][kk + t + 4];
#pragma unroll
                for (int mt = 0; mt < 2; mt++)
                    mma_tf32(o[mt][nt], af[mt], b0, b1);
            }
        }
        __syncthreads();
    }

    // Epilogue: ctx [B,S,HID]
#pragma unroll
    for (int mt = 0; mt < 2; mt++) {
#pragma unroll
        for (int hi = 0; hi < 2; hi++) {
            const int ri = mt * 2 + hi;
            float inv = 1.f / l_i[ri];
            int srow = qt * 128 + w32 + mt * 16 + g + hi * 8;
#pragma unroll
            for (int nt = 0; nt < 8; nt++) {
                float2 val;
                val.x = o[mt][nt][hi * 2 + 0] * inv;
                val.y = o[mt][nt][hi * 2 + 1] * inv;
                *(float2*)&ctx[((size_t)b * SEQ + srow) * HID + h * HD + nt * 8 + 2 * t] = val;
            }
        }
    }
}

// ---------------------------------------------------------------------------
extern "C" void kernel_launch(void* const* d_in, const int* in_sizes, int n_in,
                              void* d_out, int out_size)
{
    const float* hidden = (const float*)d_in[0];
    const float* Wq = (const float*)d_in[1];
    const float* bq = (const float*)d_in[2];
    const float* Wk = (const float*)d_in[3];
    const float* bk = (const float*)d_in[4];
    const float* Wv = (const float*)d_in[5];
    const float* bv = (const float*)d_in[6];
    const float* Wo = (const float*)d_in[7];
    const float* bo = (const float*)d_in[8];
    float* out = (float*)d_out;

    float *pQ, *pK, *pV, *pCtx;
    cudaGetSymbolAddress((void**)&pQ, g_Q);
    cudaGetSymbolAddress((void**)&pK, g_K);
    cudaGetSymbolAddress((void**)&pV, g_V);
    cudaGetSymbolAddress((void**)&pCtx, g_ctx);

    dim3 ggrid(HID / 128, MTOT / 128);  // (8, 32)

    gemm_tf32_kernel<1><<<ggrid, 256>>>(hidden, Wq, bq, pQ);
    gemm_tf32_kernel<1><<<ggrid, 256>>>(hidden, Wk, bk, pK);
    gemm_tf32_kernel<1><<<ggrid, 256>>>(hidden, Wv, bv, pV);

    {
        const int total = 2 * (BSZ * NH * SEQ) * 30;
        rope_kernel<<<(total + 255) / 256, 256>>>(pQ, pK);
    }

    {
        const int smem_bytes = (128 * 68 + 2 * 64 * 68 + 128 * 68) * sizeof(unsigned); // 104448
        cudaFuncSetAttribute(attn_tf32_kernel,
                             cudaFuncAttributeMaxDynamicSharedMemorySize,
                             smem_bytes);
        dim3 agrid(SEQ / 128, NH, BSZ);  // (16, 16, 2)
        attn_tf32_kernel<<<agrid, 128, smem_bytes>>>(pQ, pK, pV, pCtx);
    }

    gemm_tf32_kernel<0><<<ggrid, 256>>>(pCtx, Wo, bo, out);
}

// round 5
// speedup vs baseline: 5.2142x; 1.0259x over previous
#include <cuda_runtime.h>
#include <math_constants.h>

#define BSZ 2
#define SEQ 2048
#define HID 1024
#define NH 16
#define HD 64
#define MTOT (BSZ * SEQ)   // 4096

// Scratch
__device__ float g_Q[BSZ * NH * SEQ * HD];
__device__ float g_K[BSZ * NH * SEQ * HD];
__device__ float g_V[BSZ * NH * SEQ * HD];
__device__ float g_ctx[BSZ * SEQ * HID];

// omega[j] = 10000^(-j/10)
__constant__ float c_om[10] = {
    1.0f, 0.3981071705534972f, 0.15848931924611134f, 0.06309573444801933f,
    0.025118864315095794f, 0.01f, 0.003981071705534973f,
    0.0015848931924611136f, 0.0006309573444801934f, 0.00025118864315095795f};

__device__ __forceinline__ unsigned f2tf32(float x) {
    unsigned r;
    asm("cvt.rna.tf32.f32 %0, %1;" : "=r"(r) : "f"(x));
    return r;
}

__device__ __forceinline__ void mma_tf32(float c[4], const unsigned a[4],
                                         unsigned b0, unsigned b1) {
    asm volatile(
        "mma.sync.aligned.m16n8k8.row.col.f32.tf32.tf32.f32 "
        "{%0,%1,%2,%3}, {%4,%5,%6,%7}, {%8,%9}, {%0,%1,%2,%3};\n"
        : "+f"(c[0]), "+f"(c[1]), "+f"(c[2]), "+f"(c[3])
        : "r"(a[0]), "r"(a[1]), "r"(a[2]), "r"(a[3]), "r"(b0), "r"(b1));
}

__device__ __forceinline__ void cp16(void* dst, const void* src) {
    unsigned d = (unsigned)__cvta_generic_to_shared(dst);
    asm volatile("cp.async.cg.shared.global [%0], [%1], 16;\n"
                 :: "r"(d), "l"(src));
}
#define CP_COMMIT() asm volatile("cp.async.commit_group;\n" ::: "memory")
#define CP_WAIT1()  asm volatile("cp.async.wait_group 1;\n" ::: "memory")
#define CP_WAIT0()  asm volatile("cp.async.wait_group 0;\n" ::: "memory")

// ---------------------------------------------------------------------------
// tf32 GEMM, 128x128 tile, BK=32, 256 threads, double-buffered (reg prefetch).
// LAYOUT 0: row-major [B,S,HID]; LAYOUT 1: scatter [B,H,S,D].
// ROPE 1: apply axial RoPE rotation in epilogue (LAYOUT 1 only).
// ---------------------------------------------------------------------------
template <int LAYOUT, int ROPE>
__global__ void __launch_bounds__(256) gemm_tf32_kernel(
    const float* __restrict__ A, const float* __restrict__ W,
    const float* __restrict__ bias, float* __restrict__ C)
{
    extern __shared__ unsigned smg[];
    unsigned (*As)[128][36] = (unsigned(*)[128][36])smg;               // [buf][m][k]
    unsigned (*Bs)[32][136] = (unsigned(*)[32][136])(smg + 2 * 128 * 36);

    const int tid = threadIdx.x;
    const int warp = tid >> 5, lane = tid & 31;
    const int g = lane >> 2, t = lane & 3;
    const int wm = (warp >> 2) * 64;
    const int wn = (warp & 3) * 32;
    const int m0 = blockIdx.y * 128;
    const int n0 = blockIdx.x * 128;

    const int arow = tid >> 3, acg = (tid & 7) * 4;       // +32 rows per it
    const int brow = tid >> 5, bcg = (tid & 31) * 4;      // +8 rows per it

    float4 ra[4], rb[4];
    auto load_g = [&](int k0) {
#pragma unroll
        for (int it = 0; it < 4; it++)
            ra[it] = *(const float4*)&A[(size_t)(m0 + arow + it * 32) * 1024 + k0 + acg];
#pragma unroll
        for (int it = 0; it < 4; it++)
            rb[it] = *(const float4*)&W[(size_t)(k0 + brow + it * 8) * 1024 + n0 + bcg];
    };
    auto store_s = [&](int bu) {
#pragma unroll
        for (int it = 0; it < 4; it++) {
            As[bu][arow + it * 32][acg + 0] = f2tf32(ra[it].x);
            As[bu][arow + it * 32][acg + 1] = f2tf32(ra[it].y);
            As[bu][arow + it * 32][acg + 2] = f2tf32(ra[it].z);
            As[bu][arow + it * 32][acg + 3] = f2tf32(ra[it].w);
        }
#pragma unroll
        for (int it = 0; it < 4; it++) {
            Bs[bu][brow + it * 8][bcg + 0] = f2tf32(rb[it].x);
            Bs[bu][brow + it * 8][bcg + 1] = f2tf32(rb[it].y);
            Bs[bu][brow + it * 8][bcg + 2] = f2tf32(rb[it].z);
            Bs[bu][brow + it * 8][bcg + 3] = f2tf32(rb[it].w);
        }
    };

    float acc[4][4][4];
#pragma unroll
    for (int mt = 0; mt < 4; mt++)
#pragma unroll
        for (int nt = 0; nt < 4; nt++)
#pragma unroll
            for (int i = 0; i < 4; i++) acc[mt][nt][i] = 0.f;

    load_g(0);
    store_s(0);
    __syncthreads();

    int cur = 0;
    for (int k0 = 0; k0 < 1024; k0 += 32) {
        const bool more = (k0 + 32) < 1024;
        if (more) load_g(k0 + 32);

#pragma unroll
        for (int ks = 0; ks < 4; ks++) {
            const int kk = ks * 8;
            unsigned af[4][4];
#pragma unroll
            for (int mt = 0; mt < 4; mt++) {
                int r = wm + mt * 16 + g;
                af[mt][0] = As[cur][r][kk + t];
                af[mt][1] = As[cur][r + 8][kk + t];
                af[mt][2] = As[cur][r][kk + t + 4];
                af[mt][3] = As[cur][r + 8][kk + t + 4];
            }
#pragma unroll
            for (int nt = 0; nt < 4; nt++) {
                unsigned b0 = Bs[cur][kk + t][wn + nt * 8 + g];
                unsigned b1 = Bs[cur][kk + t + 4][wn + nt * 8 + g];
#pragma unroll
                for (int mt = 0; mt < 4; mt++)
                    mma_tf32(acc[mt][nt], af[mt], b0, b1);
            }
        }

        if (more) store_s(cur ^ 1);
        __syncthreads();
        cur ^= 1;
    }

    // Epilogue (+bias, optional RoPE, layout)
#pragma unroll
    for (int mt = 0; mt < 4; mt++) {
#pragma unroll
        for (int hi = 0; hi < 2; hi++) {
            int m = m0 + wm + mt * 16 + g + hi * 8;
            int s = m & (SEQ - 1);
            int frame = s >> 8;
            int rem = s & 255;
            int hp = rem >> 4;
            int wp = rem & 15;
#pragma unroll
            for (int nt = 0; nt < 4; nt++) {
                int n = n0 + wn + nt * 8 + 2 * t;
                float2 val;
                val.x = acc[mt][nt][hi * 2 + 0] + bias[n];
                val.y = acc[mt][nt][hi * 2 + 1] + bias[n + 1];
                if (ROPE) {
                    int d = n & (HD - 1);
                    if (d < 60) {
                        int seg = d / 20;
                        int dl = d - seg * 20;        // even
                        int je = dl % 10;             // even -> je+1 <= 9
                        float pos = (float)(seg == 0 ? frame : (seg == 1 ? hp : wp));
                        float se, ce, so, co;
                        __sincosf(pos * c_om[je], &se, &ce);
                        __sincosf(pos * c_om[je + 1], &so, &co);
                        float xo = val.x, yo = val.y;
                        val.x = xo * ce - yo * se;
                        val.y = yo * co + xo * so;
                    }
                }
                if (LAYOUT == 0) {
                    *(float2*)&C[(size_t)m * 1024 + n] = val;
                } else {
                    int b = m >> 11;
                    int h = n >> 6;
                    int d = n & (HD - 1);
                    *(float2*)&C[((((size_t)b * NH + h) * SEQ + s) * HD) + d] = val;
                }
            }
        }
    }
}

// ---------------------------------------------------------------------------
// Flash attention, tf32 mma, cp.async double-buffered K/V (raw f32 in smem,
// cvt at fragment load). 128 threads, 128 queries/block, 64-key tiles.
// Smem (words): Qs[128][68] tf32 | Kr[2][64][72] f32 | Vr[2][64][72] f32 |
//               Ss[128][68] tf32   -> 143,360 B
// ---------------------------------------------------------------------------
__global__ void __launch_bounds__(128) attn_tf32_kernel(
    const float* __restrict__ Q, const float* __restrict__ K,
    const float* __restrict__ V, float* __restrict__ ctx)
{
    extern __shared__ float smf[];
    unsigned (*Qs)[68] = (unsigned(*)[68])smf;
    float (*Kr)[64][72] = (float(*)[64][72])(smf + 128 * 68);
    float (*Vr)[64][72] = (float(*)[64][72])(smf + 128 * 68 + 2 * 64 * 72);
    unsigned (*Ss)[68] = (unsigned(*)[68])(smf + 128 * 68 + 4 * 64 * 72);

    const int tid = threadIdx.x;
    const int warp = tid >> 5, lane = tid & 31;
    const int g = lane >> 2, t = lane & 3;
    const int w32 = warp * 32;
    const int qt = blockIdx.x;
    const int h = blockIdx.y;
    const int b = blockIdx.z;

    const float* Qb = Q + (((size_t)b * NH + h) * SEQ + qt * 128) * HD;
    const float* Kb = K + ((size_t)b * NH + h) * SEQ * HD;
    const float* Vb = V + ((size_t)b * NH + h) * SEQ * HD;

    auto issue = [&](int j0, int bu) {
#pragma unroll
        for (int i = 0; i < 8; i++) {
            int c = tid + i * 128;           // 0..1023
            int row = c >> 4;
            int col = (c & 15) * 4;
            cp16(&Kr[bu][row][col], Kb + (size_t)(j0 + row) * HD + col);
            cp16(&Vr[bu][row][col], Vb + (size_t)(j0 + row) * HD + col);
        }
        CP_COMMIT();
    };

    // Q tile 128x64 -> tf32
#pragma unroll
    for (int it = 0; it < 16; it++) {
        int l = tid + it * 128;
        int row = l >> 4;
        int cg = (l & 15) * 4;
        float4 v = *(const float4*)&Qb[(size_t)row * HD + cg];
        Qs[row][cg + 0] = f2tf32(v.x);
        Qs[row][cg + 1] = f2tf32(v.y);
        Qs[row][cg + 2] = f2tf32(v.z);
        Qs[row][cg + 3] = f2tf32(v.w);
    }

    issue(0, 0);

    float m_i[4], l_i[4], o[2][8][4];
#pragma unroll
    for (int i = 0; i < 4; i++) { m_i[i] = -CUDART_INF_F; l_i[i] = 0.f; }
#pragma unroll
    for (int mt = 0; mt < 2; mt++)
#pragma unroll
        for (int nt = 0; nt < 8; nt++)
#pragma unroll
            for (int i = 0; i < 4; i++) o[mt][nt][i] = 0.f;

    for (int jt = 0; jt < SEQ / 64; jt++) {
        const int bu = jt & 1;
        if (jt + 1 < SEQ / 64) {
            issue((jt + 1) * 64, bu ^ 1);
            CP_WAIT1();
        } else {
            CP_WAIT0();
        }
        __syncthreads();

        // S = Q K^T
        float sc[2][8][4];
#pragma unroll
        for (int mt = 0; mt < 2; mt++)
#pragma unroll
            for (int nt = 0; nt < 8; nt++)
#pragma unroll
                for (int i = 0; i < 4; i++) sc[mt][nt][i] = 0.f;

#pragma unroll
        for (int ks = 0; ks < 8; ks++) {
            const int kk = ks * 8;
            unsigned af[2][4];
#pragma unroll
            for (int mt = 0; mt < 2; mt++) {
                int r = w32 + mt * 16 + g;
                af[mt][0] = Qs[r][kk + t];
                af[mt][1] = Qs[r + 8][kk + t];
                af[mt][2] = Qs[r][kk + t + 4];
                af[mt][3] = Qs[r + 8][kk + t + 4];
            }
#pragma unroll
            for (int nt = 0; nt < 8; nt++) {
                unsigned b0 = f2tf32(Kr[bu][nt * 8 + g][kk + t]);
                unsigned b1 = f2tf32(Kr[bu][nt * 8 + g][kk + t + 4]);
#pragma unroll
                for (int mt = 0; mt < 2; mt++)
                    mma_tf32(sc[mt][nt], af[mt], b0, b1);
            }
        }

        // Online softmax; write P (tf32) to Ss
#pragma unroll
        for (int mt = 0; mt < 2; mt++) {
#pragma unroll
            for (int hi = 0; hi < 2; hi++) {
                const int ri = mt * 2 + hi;
                float pm = -CUDART_INF_F;
#pragma unroll
                for (int nt = 0; nt < 8; nt++) {
                    sc[mt][nt][hi * 2 + 0] *= 0.125f;
                    sc[mt][nt][hi * 2 + 1] *= 0.125f;
                    pm = fmaxf(pm, fmaxf(sc[mt][nt][hi * 2], sc[mt][nt][hi * 2 + 1]));
                }
                pm = fmaxf(pm, __shfl_xor_sync(0xffffffffu, pm, 1));
                pm = fmaxf(pm, __shfl_xor_sync(0xffffffffu, pm, 2));

                float mn = fmaxf(m_i[ri], pm);
                float corr = __expf(m_i[ri] - mn);
                m_i[ri] = mn;

                float ps = 0.f;
                int row = w32 + mt * 16 + g + hi * 8;
#pragma unroll
                for (int nt = 0; nt < 8; nt++) {
                    float p0 = __expf(sc[mt][nt][hi * 2 + 0] - mn);
                    float p1 = __expf(sc[mt][nt][hi * 2 + 1] - mn);
                    ps += p0 + p1;
                    Ss[row][nt * 8 + 2 * t + 0] = f2tf32(p0);
                    Ss[row][nt * 8 + 2 * t + 1] = f2tf32(p1);
                }
                ps += __shfl_xor_sync(0xffffffffu, ps, 1);
                ps += __shfl_xor_sync(0xffffffffu, ps, 2);
                l_i[ri] = l_i[ri] * corr + ps;

#pragma unroll
                for (int nt = 0; nt < 8; nt++) {
                    o[mt][nt][hi * 2 + 0] *= corr;
                    o[mt][nt][hi * 2 + 1] *= corr;
                }
            }
        }
        __syncwarp();

        // O += P V
#pragma unroll
        for (int ks = 0; ks < 8; ks++) {
            const int kk = ks * 8;
            unsigned af[2][4];
#pragma unroll
            for (int mt = 0; mt < 2; mt++) {
                int r = w32 + mt * 16 + g;
                af[mt][0] = Ss[r][kk + t];
                af[mt][1] = Ss[r + 8][kk + t];
                af[mt][2] = Ss[r][kk + t + 4];
                af[mt][3] = Ss[r + 8][kk + t + 4];
            }
#pragma unroll
            for (int nt = 0; nt < 8; nt++) {
                unsigned b0 = f2tf32(Vr[bu][kk + t][nt * 8 + g]);
                unsigned b1 = f2tf32(Vr[bu][kk + t + 4][nt * 8 + g]);
#pragma unroll
                for (int mt = 0; mt < 2; mt++)
                    mma_tf32(o[mt][nt], af[mt], b0, b1);
            }
        }
        __syncthreads();
    }

    // Epilogue: ctx [B,S,HID]
#pragma unroll
    for (int mt = 0; mt < 2; mt++) {
#pragma unroll
        for (int hi = 0; hi < 2; hi++) {
            const int ri = mt * 2 + hi;
            float inv = 1.f / l_i[ri];
            int srow = qt * 128 + w32 + mt * 16 + g + hi * 8;
#pragma unroll
            for (int nt = 0; nt < 8; nt++) {
                float2 val;
                val.x = o[mt][nt][hi * 2 + 0] * inv;
                val.y = o[mt][nt][hi * 2 + 1] * inv;
                *(float2*)&ctx[((size_t)b * SEQ + srow) * HID + h * HD + nt * 8 + 2 * t] = val;
            }
        }
    }
}

// ---------------------------------------------------------------------------
extern "C" void kernel_launch(void* const* d_in, const int* in_sizes, int n_in,
                              void* d_out, int out_size)
{
    const float* hidden = (const float*)d_in[0];
    const float* Wq = (const float*)d_in[1];
    const float* bq = (const float*)d_in[2];
    const float* Wk = (const float*)d_in[3];
    const float* bk = (const float*)d_in[4];
    const float* Wv = (const float*)d_in[5];
    const float* bv = (const float*)d_in[6];
    const float* Wo = (const float*)d_in[7];
    const float* bo = (const float*)d_in[8];
    float* out = (float*)d_out;

    float *pQ, *pK, *pV, *pCtx;
    cudaGetSymbolAddress((void**)&pQ, g_Q);
    cudaGetSymbolAddress((void**)&pK, g_K);
    cudaGetSymbolAddress((void**)&pV, g_V);
    cudaGetSymbolAddress((void**)&pCtx, g_ctx);

    const int gsmem = (2 * 128 * 36 + 2 * 32 * 136) * 4;   // 71,680 B
    cudaFuncSetAttribute(gemm_tf32_kernel<1, 1>,
                         cudaFuncAttributeMaxDynamicSharedMemorySize, gsmem);
    cudaFuncSetAttribute(gemm_tf32_kernel<1, 0>,
                         cudaFuncAttributeMaxDynamicSharedMemorySize, gsmem);
    cudaFuncSetAttribute(gemm_tf32_kernel<0, 0>,
                         cudaFuncAttributeMaxDynamicSharedMemorySize, gsmem);

    dim3 ggrid(HID / 128, MTOT / 128);  // (8, 32)

    gemm_tf32_kernel<1, 1><<<ggrid, 256, gsmem>>>(hidden, Wq, bq, pQ);
    gemm_tf32_kernel<1, 1><<<ggrid, 256, gsmem>>>(hidden, Wk, bk, pK);
    gemm_tf32_kernel<1, 0><<<ggrid, 256, gsmem>>>(hidden, Wv, bv, pV);

    {
        const int smem_bytes = (128 * 68 + 4 * 64 * 72 + 128 * 68) * 4;  // 143,360
        cudaFuncSetAttribute(attn_tf32_kernel,
                             cudaFuncAttributeMaxDynamicSharedMemorySize,
                             smem_bytes);
        dim3 agrid(SEQ / 128, NH, BSZ);  // (16, 16, 2)
        attn_tf32_kernel<<<agrid, 128, smem_bytes>>>(pQ, pK, pV, pCtx);
    }

    gemm_tf32_kernel<0, 0><<<ggrid, 256, gsmem>>>(pCtx, Wo, bo, out);
}